// round 2
// baseline (speedup 1.0000x reference)
#include <cuda_runtime.h>
#include <math.h>

#define BB 4
#define SS 4096
#define DD 1024
#define DQK 64

// ---------------- scratch (alloc-free: __device__ globals) ----------------
static __device__ float g_Q[BB * SS * DQK];            // 4 MB   (pre-scaled by 1/8)
static __device__ float g_K[BB * SS * DQK];            // 4 MB
static __device__ float g_P[(size_t)BB * SS * SS];     // 268 MB (raw scores, then P)
static __device__ float g_m[BB * SS];
static __device__ float g_l[BB * SS];

// =====================================================================
// Kernel 1: fused Q/K projection.  M=B*S=16384 rows, N=128 (64 q | 64 k), K=1024.
// Block: 64 rows x 128 cols, 256 threads, 4x8 micro-tile.
// =====================================================================
__global__ __launch_bounds__(256) void proj_kernel(const float* __restrict__ enc,
                                                   const float* __restrict__ Wq,
                                                   const float* __restrict__ Wk) {
    __shared__ float As[32][65];    // [k][row]
    __shared__ float Ws[32][129];   // [k][col]
    const int m0 = blockIdx.x * 64;
    const int tid = threadIdx.x;
    const int tx = tid & 15;        // col group
    const int ty = tid >> 4;        // row group

    float acc[4][8];
#pragma unroll
    for (int i = 0; i < 4; i++)
#pragma unroll
        for (int j = 0; j < 8; j++) acc[i][j] = 0.0f;

    for (int k0 = 0; k0 < DD; k0 += 32) {
        // load A tile: 64 rows x 32 k  (512 float4)
#pragma unroll
        for (int t = 0; t < 2; t++) {
            int f = tid + t * 256;          // 0..511
            int r = f >> 3;                 // row 0..63
            int c4 = f & 7;                 // float4 index in k
            float4 v = *(const float4*)&enc[(size_t)(m0 + r) * DD + k0 + c4 * 4];
            As[c4 * 4 + 0][r] = v.x;
            As[c4 * 4 + 1][r] = v.y;
            As[c4 * 4 + 2][r] = v.z;
            As[c4 * 4 + 3][r] = v.w;
        }
        // load W tile: 128 cols x 32 k  (1024 float4)
#pragma unroll
        for (int t = 0; t < 4; t++) {
            int f = tid + t * 256;          // 0..1023
            int col = f >> 3;               // 0..127
            int c4 = f & 7;
            const float* src = (col < 64)
                ? &Wq[(size_t)col * DD + k0 + c4 * 4]
                : &Wk[(size_t)(col - 64) * DD + k0 + c4 * 4];
            float4 v = *(const float4*)src;
            Ws[c4 * 4 + 0][col] = v.x;
            Ws[c4 * 4 + 1][col] = v.y;
            Ws[c4 * 4 + 2][col] = v.z;
            Ws[c4 * 4 + 3][col] = v.w;
        }
        __syncthreads();
#pragma unroll
        for (int kk = 0; kk < 32; kk++) {
            float a[4], w[8];
#pragma unroll
            for (int i = 0; i < 4; i++) a[i] = As[kk][ty * 4 + i];
#pragma unroll
            for (int j = 0; j < 8; j++) w[j] = Ws[kk][tx * 8 + j];
#pragma unroll
            for (int i = 0; i < 4; i++)
#pragma unroll
                for (int j = 0; j < 8; j++) acc[i][j] = fmaf(a[i], w[j], acc[i][j]);
        }
        __syncthreads();
    }

    // write out: cols < 64 -> Q (scaled by 1/8), cols >= 64 -> K
#pragma unroll
    for (int i = 0; i < 4; i++) {
        int row = m0 + ty * 4 + i;
#pragma unroll
        for (int j = 0; j < 8; j++) {
            int col = tx * 8 + j;
            if (col < 64) g_Q[(size_t)row * DQK + col] = acc[i][j] * 0.125f;
            else          g_K[(size_t)row * DQK + (col - 64)] = acc[i][j];
        }
    }
}

// =====================================================================
// Kernel 2: raw scores + online row stats.
// Block = (qt, b): 64-query tile, loops key tiles kt = 0..(qt|1)
// (rounded up to odd so every 128-wide span read by the PV GEMM is defined).
// Writes raw scores (masked entries = -1e9) to g_P; writes final m,l.
// =====================================================================
__global__ __launch_bounds__(256) void score_kernel() {
    const int qt = (int)gridDim.x - 1 - (int)blockIdx.x;   // heavy tiles first
    const int b = blockIdx.y;
    const int q0 = qt * 64;
    const int tid = threadIdx.x;
    const int tx = tid & 15;
    const int ty = tid >> 4;

    __shared__ float Qs[64][68];   // [e][row]
    __shared__ float Ks[64][68];   // [e][row]
    __shared__ float red_m[64][16];
    __shared__ float red_l[64][16];

    // load Q tile (transposed into [e][row])
#pragma unroll
    for (int t = 0; t < 4; t++) {
        int f = tid + t * 256;            // 0..1023 float4s
        int r = f >> 4;                   // row 0..63
        int e4 = f & 15;
        float4 v = *(const float4*)&g_Q[(size_t)(b * SS + q0 + r) * DQK + e4 * 4];
        Qs[e4 * 4 + 0][r] = v.x;
        Qs[e4 * 4 + 1][r] = v.y;
        Qs[e4 * 4 + 2][r] = v.z;
        Qs[e4 * 4 + 3][r] = v.w;
    }

    float m_i[4], l_i[4];
#pragma unroll
    for (int i = 0; i < 4; i++) { m_i[i] = -INFINITY; l_i[i] = 0.0f; }

    const int kt_end = (qt | 1);
    for (int kt = 0; kt <= kt_end; kt++) {
        const int k0 = kt * 64;
        __syncthreads();   // protect Ks reuse
#pragma unroll
        for (int t = 0; t < 4; t++) {
            int f = tid + t * 256;
            int r = f >> 4;
            int e4 = f & 15;
            float4 v = *(const float4*)&g_K[(size_t)(b * SS + k0 + r) * DQK + e4 * 4];
            Ks[e4 * 4 + 0][r] = v.x;
            Ks[e4 * 4 + 1][r] = v.y;
            Ks[e4 * 4 + 2][r] = v.z;
            Ks[e4 * 4 + 3][r] = v.w;
        }
        __syncthreads();

        float acc[4][4];
#pragma unroll
        for (int i = 0; i < 4; i++)
#pragma unroll
            for (int j = 0; j < 4; j++) acc[i][j] = 0.0f;

#pragma unroll
        for (int e = 0; e < 64; e++) {
            float4 a = *(const float4*)&Qs[e][ty * 4];
            float4 kb = *(const float4*)&Ks[e][tx * 4];
            float av[4] = {a.x, a.y, a.z, a.w};
            float bv[4] = {kb.x, kb.y, kb.z, kb.w};
#pragma unroll
            for (int i = 0; i < 4; i++)
#pragma unroll
                for (int j = 0; j < 4; j++) acc[i][j] = fmaf(av[i], bv[j], acc[i][j]);
        }

#pragma unroll
        for (int i = 0; i < 4; i++) {
            const int q = q0 + ty * 4 + i;
            float s[4];
#pragma unroll
            for (int j = 0; j < 4; j++) {
                int kj = k0 + tx * 4 + j;
                s[j] = (kj <= q) ? acc[i][j] : -1e9f;
            }
            float tmax = fmaxf(fmaxf(s[0], s[1]), fmaxf(s[2], s[3]));
            float nm = fmaxf(m_i[i], tmax);
            float l = l_i[i] * __expf(m_i[i] - nm);
#pragma unroll
            for (int j = 0; j < 4; j++) l += __expf(s[j] - nm);
            m_i[i] = nm;
            l_i[i] = l;
            // write raw score tile (float4, cols contiguous)
            *(float4*)&g_P[((size_t)(b * SS + q)) * SS + k0 + tx * 4] =
                make_float4(s[0], s[1], s[2], s[3]);
        }
    }

    // block reduction of (m, l) across the 16 tx lanes per row
#pragma unroll
    for (int i = 0; i < 4; i++) {
        red_m[ty * 4 + i][tx] = m_i[i];
        red_l[ty * 4 + i][tx] = l_i[i];
    }
    __syncthreads();
    if (tid < 64) {
        int row = tid;
        float M = -INFINITY;
#pragma unroll
        for (int t = 0; t < 16; t++) M = fmaxf(M, red_m[row][t]);
        float L = 0.0f;
#pragma unroll
        for (int t = 0; t < 16; t++) L += red_l[row][t] * __expf(red_m[row][t] - M);
        g_m[b * SS + q0 + row] = M;
        g_l[b * SS + q0 + row] = L;
    }
}

// =====================================================================
// Kernel 3: normalize   P = exp(S - m) / l  over the defined 128-span.
// =====================================================================
__global__ __launch_bounds__(256) void norm_kernel() {
    const int qt = blockIdx.x;
    const int b = blockIdx.y;
    const int q0 = qt * 64;
    const int ncols = ((qt | 1) + 1) * 64;
    const int tid = threadIdx.x;

    for (int r = 0; r < 64; r++) {
        const int row = q0 + r;
        const float m = g_m[b * SS + row];
        const float inv_l = 1.0f / g_l[b * SS + row];
        float* base = &g_P[((size_t)(b * SS + row)) * SS];
        for (int c = tid * 4; c < ncols; c += 1024) {
            float4 v = *(float4*)&base[c];
            v.x = __expf(v.x - m) * inv_l;
            v.y = __expf(v.y - m) * inv_l;
            v.z = __expf(v.z - m) * inv_l;
            v.w = __expf(v.w - m) * inv_l;
            *(float4*)&base[c] = v;
        }
    }
}

// =====================================================================
// Kernel 4: O[b] = P[b] @ enc[b], causal (k only up to (rt+1)*128).
// 128x128 output tile, KC=8, double-buffered smem, 8x8 micro-tile.
// =====================================================================
__global__ __launch_bounds__(256, 2) void pv_kernel(const float* __restrict__ enc,
                                                    float* __restrict__ out) {
    const int ct = blockIdx.x;                                  // 0..7
    const int rt = (int)gridDim.y - 1 - (int)blockIdx.y;        // heavy first
    const int b = blockIdx.z;
    const int q0 = rt * 128, c0 = ct * 128;
    const int tid = threadIdx.x;
    const int tx = tid & 15;
    const int ty = tid >> 4;

    __shared__ float Ps[2][8][132];   // [kk][row]
    __shared__ float Vs[2][8][132];   // [kk][col]

    float acc[8][8];
#pragma unroll
    for (int i = 0; i < 8; i++)
#pragma unroll
        for (int j = 0; j < 8; j++) acc[i][j] = 0.0f;

    const int nk = (rt + 1) * 16;   // number of 8-wide k steps

    // loader roles
    const int pr = tid >> 1;        // P row 0..127
    const int pc4 = tid & 1;        // P float4 col 0..1
    const int vk = tid >> 5;        // V k-row 0..7
    const int vc4 = tid & 31;       // V float4 col 0..31
    const size_t Pbase = ((size_t)(b * SS + q0 + pr)) * SS;

    // preload k-step 0
    {
        float4 p0 = *(const float4*)&g_P[Pbase + pc4 * 4];
        float4 v0 = *(const float4*)&enc[((size_t)(b * SS + vk)) * DD + c0 + vc4 * 4];
        Ps[0][pc4 * 4 + 0][pr] = p0.x;
        Ps[0][pc4 * 4 + 1][pr] = p0.y;
        Ps[0][pc4 * 4 + 2][pr] = p0.z;
        Ps[0][pc4 * 4 + 3][pr] = p0.w;
        *(float4*)&Vs[0][vk][vc4 * 4] = v0;
    }
    __syncthreads();

    int buf = 0;
    for (int kt = 0; kt < nk; kt++) {
        float4 pn, vn;
        const bool has_next = (kt + 1 < nk);
        if (has_next) {
            const int k0 = (kt + 1) * 8;
            pn = *(const float4*)&g_P[Pbase + k0 + pc4 * 4];
            vn = *(const float4*)&enc[((size_t)(b * SS + k0 + vk)) * DD + c0 + vc4 * 4];
        }
#pragma unroll
        for (int kk = 0; kk < 8; kk++) {
            float4 a0 = *(const float4*)&Ps[buf][kk][ty * 4];
            float4 a1 = *(const float4*)&Ps[buf][kk][64 + ty * 4];
            float4 b0 = *(const float4*)&Vs[buf][kk][tx * 4];
            float4 b1 = *(const float4*)&Vs[buf][kk][64 + tx * 4];
            float a[8] = {a0.x, a0.y, a0.z, a0.w, a1.x, a1.y, a1.z, a1.w};
            float bb[8] = {b0.x, b0.y, b0.z, b0.w, b1.x, b1.y, b1.z, b1.w};
#pragma unroll
            for (int i = 0; i < 8; i++)
#pragma unroll
                for (int j = 0; j < 8; j++) acc[i][j] = fmaf(a[i], bb[j], acc[i][j]);
        }
        if (has_next) {
            Ps[buf ^ 1][pc4 * 4 + 0][pr] = pn.x;
            Ps[buf ^ 1][pc4 * 4 + 1][pr] = pn.y;
            Ps[buf ^ 1][pc4 * 4 + 2][pr] = pn.z;
            Ps[buf ^ 1][pc4 * 4 + 3][pr] = pn.w;
            *(float4*)&Vs[buf ^ 1][vk][vc4 * 4] = vn;
            __syncthreads();
            buf ^= 1;
        }
    }

    // epilogue
#pragma unroll
    for (int ih = 0; ih < 2; ih++) {
#pragma unroll
        for (int i = 0; i < 4; i++) {
            const int r = q0 + ih * 64 + ty * 4 + i;
            const size_t ro = ((size_t)(b * SS + r)) * DD + c0;
            const int ai = ih * 4 + i;
            *(float4*)&out[ro + tx * 4] =
                make_float4(acc[ai][0], acc[ai][1], acc[ai][2], acc[ai][3]);
            *(float4*)&out[ro + 64 + tx * 4] =
                make_float4(acc[ai][4], acc[ai][5], acc[ai][6], acc[ai][7]);
        }
    }
}

// =====================================================================
extern "C" void kernel_launch(void* const* d_in, const int* in_sizes, int n_in,
                              void* d_out, int out_size) {
    (void)in_sizes; (void)n_in; (void)out_size;
    const float* enc = (const float*)d_in[0];
    const float* Wq  = (const float*)d_in[1];
    const float* Wk  = (const float*)d_in[2];
    float* out = (float*)d_out;

    proj_kernel<<<dim3((BB * SS) / 64), 256>>>(enc, Wq, Wk);
    score_kernel<<<dim3(SS / 64, BB), 256>>>();
    norm_kernel<<<dim3(SS / 64, BB), 256>>>();
    pv_kernel<<<dim3(DD / 128, SS / 128, BB), 256>>>(enc, out);
}

// round 8
// speedup vs baseline: 1.6313x; 1.6313x over previous
#include <cuda_runtime.h>
#include <cuda_bf16.h>
#include <cstdint>
#include <math.h>

#define BB 4
#define SS 4096
#define DD 1024
#define DQK 64

// ---------------- scratch (alloc-free: __device__ globals) ----------------
static __device__ float g_Q[BB * SS * DQK];            // 4 MB (pre-scaled by 1/8)
static __device__ float g_K[BB * SS * DQK];            // 4 MB
static __device__ float g_P[(size_t)BB * SS * SS];     // 268 MB raw scores
static __device__ float g_m[BB * SS];
static __device__ float g_l[BB * SS];

// =====================================================================
// Kernel 1: fused Q/K projection (scalar)
// =====================================================================
__global__ __launch_bounds__(256) void proj_kernel(const float* __restrict__ enc,
                                                   const float* __restrict__ Wq,
                                                   const float* __restrict__ Wk) {
    __shared__ float As[32][65];
    __shared__ float Ws[32][129];
    const int m0 = blockIdx.x * 64;
    const int tid = threadIdx.x;
    const int tx = tid & 15;
    const int ty = tid >> 4;

    float acc[4][8];
#pragma unroll
    for (int i = 0; i < 4; i++) {
#pragma unroll
        for (int j = 0; j < 8; j++) { acc[i][j] = 0.0f; }
    }

    for (int k0 = 0; k0 < DD; k0 += 32) {
#pragma unroll
        for (int t = 0; t < 2; t++) {
            int f = tid + t * 256;
            int r = f >> 3;
            int c4 = f & 7;
            float4 v = *(const float4*)&enc[(size_t)(m0 + r) * DD + k0 + c4 * 4];
            As[c4 * 4 + 0][r] = v.x;
            As[c4 * 4 + 1][r] = v.y;
            As[c4 * 4 + 2][r] = v.z;
            As[c4 * 4 + 3][r] = v.w;
        }
#pragma unroll
        for (int t = 0; t < 4; t++) {
            int f = tid + t * 256;
            int col = f >> 3;
            int c4 = f & 7;
            const float* src;
            if (col < 64) { src = &Wq[(size_t)col * DD + k0 + c4 * 4]; }
            else          { src = &Wk[(size_t)(col - 64) * DD + k0 + c4 * 4]; }
            float4 v = *(const float4*)src;
            Ws[c4 * 4 + 0][col] = v.x;
            Ws[c4 * 4 + 1][col] = v.y;
            Ws[c4 * 4 + 2][col] = v.z;
            Ws[c4 * 4 + 3][col] = v.w;
        }
        __syncthreads();
#pragma unroll
        for (int kk = 0; kk < 32; kk++) {
            float a[4];
            float w[8];
#pragma unroll
            for (int i = 0; i < 4; i++) { a[i] = As[kk][ty * 4 + i]; }
#pragma unroll
            for (int j = 0; j < 8; j++) { w[j] = Ws[kk][tx * 8 + j]; }
#pragma unroll
            for (int i = 0; i < 4; i++) {
#pragma unroll
                for (int j = 0; j < 8; j++) { acc[i][j] = fmaf(a[i], w[j], acc[i][j]); }
            }
        }
        __syncthreads();
    }
#pragma unroll
    for (int i = 0; i < 4; i++) {
        int row = m0 + ty * 4 + i;
#pragma unroll
        for (int j = 0; j < 8; j++) {
            int col = tx * 8 + j;
            if (col < 64) { g_Q[(size_t)row * DQK + col] = acc[i][j] * 0.125f; }
            else          { g_K[(size_t)row * DQK + (col - 64)] = acc[i][j]; }
        }
    }
}

// =====================================================================
// Kernel 2: raw scores + online row stats (scalar). Masked = -1e9,
// written over the 128-padded causal span.
// =====================================================================
__global__ __launch_bounds__(256) void score_kernel() {
    const int qt = (int)gridDim.x - 1 - (int)blockIdx.x;
    const int b = blockIdx.y;
    const int q0 = qt * 64;
    const int tid = threadIdx.x;
    const int tx = tid & 15;
    const int ty = tid >> 4;

    __shared__ float Qs[64][68];
    __shared__ float Ks[64][68];
    __shared__ float red_m[64][16];
    __shared__ float red_l[64][16];

#pragma unroll
    for (int t = 0; t < 4; t++) {
        int f = tid + t * 256;
        int r = f >> 4;
        int e4 = f & 15;
        float4 v = *(const float4*)&g_Q[(size_t)(b * SS + q0 + r) * DQK + e4 * 4];
        Qs[e4 * 4 + 0][r] = v.x;
        Qs[e4 * 4 + 1][r] = v.y;
        Qs[e4 * 4 + 2][r] = v.z;
        Qs[e4 * 4 + 3][r] = v.w;
    }

    float m_i[4];
    float l_i[4];
#pragma unroll
    for (int i = 0; i < 4; i++) { m_i[i] = -INFINITY; l_i[i] = 0.0f; }

    const int kt_end = (qt | 1);
    for (int kt = 0; kt <= kt_end; kt++) {
        const int k0 = kt * 64;
        __syncthreads();
#pragma unroll
        for (int t = 0; t < 4; t++) {
            int f = tid + t * 256;
            int r = f >> 4;
            int e4 = f & 15;
            float4 v = *(const float4*)&g_K[(size_t)(b * SS + k0 + r) * DQK + e4 * 4];
            Ks[e4 * 4 + 0][r] = v.x;
            Ks[e4 * 4 + 1][r] = v.y;
            Ks[e4 * 4 + 2][r] = v.z;
            Ks[e4 * 4 + 3][r] = v.w;
        }
        __syncthreads();

        float acc[4][4];
#pragma unroll
        for (int i = 0; i < 4; i++) {
#pragma unroll
            for (int j = 0; j < 4; j++) { acc[i][j] = 0.0f; }
        }

#pragma unroll
        for (int e = 0; e < 64; e++) {
            float4 a = *(const float4*)&Qs[e][ty * 4];
            float4 kb = *(const float4*)&Ks[e][tx * 4];
            float av[4];
            float bv[4];
            av[0] = a.x; av[1] = a.y; av[2] = a.z; av[3] = a.w;
            bv[0] = kb.x; bv[1] = kb.y; bv[2] = kb.z; bv[3] = kb.w;
#pragma unroll
            for (int i = 0; i < 4; i++) {
#pragma unroll
                for (int j = 0; j < 4; j++) { acc[i][j] = fmaf(av[i], bv[j], acc[i][j]); }
            }
        }

#pragma unroll
        for (int i = 0; i < 4; i++) {
            const int q = q0 + ty * 4 + i;
            float sv[4];
#pragma unroll
            for (int j = 0; j < 4; j++) {
                int kj = k0 + tx * 4 + j;
                sv[j] = (kj <= q) ? acc[i][j] : -1e9f;
            }
            float tmax = fmaxf(fmaxf(sv[0], sv[1]), fmaxf(sv[2], sv[3]));
            float nm = fmaxf(m_i[i], tmax);
            float l = l_i[i] * __expf(m_i[i] - nm);
#pragma unroll
            for (int j = 0; j < 4; j++) { l += __expf(sv[j] - nm); }
            m_i[i] = nm;
            l_i[i] = l;
            *(float4*)&g_P[((size_t)(b * SS + q)) * SS + k0 + tx * 4] =
                make_float4(sv[0], sv[1], sv[2], sv[3]);
        }
    }

#pragma unroll
    for (int i = 0; i < 4; i++) {
        red_m[ty * 4 + i][tx] = m_i[i];
        red_l[ty * 4 + i][tx] = l_i[i];
    }
    __syncthreads();
    if (tid < 64) {
        int row = tid;
        float M = -INFINITY;
#pragma unroll
        for (int t = 0; t < 16; t++) { M = fmaxf(M, red_m[row][t]); }
        float L = 0.0f;
#pragma unroll
        for (int t = 0; t < 16; t++) { L += red_l[row][t] * __expf(red_m[row][t] - M); }
        g_m[b * SS + q0 + row] = M;
        g_l[b * SS + q0 + row] = L;
    }
}

// =====================================================================
// Tensor-core PV: O[b] = softmax(S) @ enc[b], bf16 3-split mma.sync.
// exp((s-m))/l applied in the loader (no separate norm pass).
// =====================================================================
#define PSTRIDE 40    // bf16 units per P row  (80 B)
#define VSTRIDE 136   // bf16 units per V row  (272 B)

__device__ __forceinline__ void ldsm4(uint32_t* r, const __nv_bfloat16* p) {
    uint32_t a = (uint32_t)__cvta_generic_to_shared((void*)p);
    asm volatile("ldmatrix.sync.aligned.m8n8.x4.shared.b16 {%0,%1,%2,%3}, [%4];"
                 : "=r"(r[0]), "=r"(r[1]), "=r"(r[2]), "=r"(r[3])
                 : "r"(a));
}

__device__ __forceinline__ void ldsm4t(uint32_t* r, const __nv_bfloat16* p) {
    uint32_t a = (uint32_t)__cvta_generic_to_shared((void*)p);
    asm volatile("ldmatrix.sync.aligned.m8n8.x4.trans.shared.b16 {%0,%1,%2,%3}, [%4];"
                 : "=r"(r[0]), "=r"(r[1]), "=r"(r[2]), "=r"(r[3])
                 : "r"(a));
}

__device__ __forceinline__ void mma16816(float* c, const uint32_t* a,
                                         uint32_t b0, uint32_t b1) {
    asm volatile(
        "mma.sync.aligned.m16n8k16.row.col.f32.bf16.bf16.f32 "
        "{%0,%1,%2,%3}, {%4,%5,%6,%7}, {%8,%9}, {%0,%1,%2,%3};"
        : "+f"(c[0]), "+f"(c[1]), "+f"(c[2]), "+f"(c[3])
        : "r"(a[0]), "r"(a[1]), "r"(a[2]), "r"(a[3]), "r"(b0), "r"(b1));
}

__device__ __forceinline__ uint32_t pack2bf(float x, float y) {
    __nv_bfloat162 h;
    h.x = __float2bfloat16(x);
    h.y = __float2bfloat16(y);
    uint32_t u;
    memcpy(&u, &h, 4);
    return u;
}

__global__ __launch_bounds__(256, 2) void pv_kernel(const float* __restrict__ enc,
                                                    float* __restrict__ out) {
    const int ct = blockIdx.x;                               // dv tile 0..7
    const int rt = (int)gridDim.y - 1 - (int)blockIdx.y;     // heavy tiles first
    const int b  = blockIdx.z;
    const int q0 = rt * 128;
    const int c0 = ct * 128;
    const int tid = threadIdx.x;
    const int lane = tid & 31;
    const int wid = tid >> 5;
    const int wm = (wid & 3) * 32;      // warp row offset
    const int wn = (wid >> 2) * 64;     // warp col offset

    __shared__ __align__(16) __nv_bfloat16 sPh[128 * PSTRIDE];
    __shared__ __align__(16) __nv_bfloat16 sPl[128 * PSTRIDE];
    __shared__ __align__(16) __nv_bfloat16 sVh[32 * VSTRIDE];
    __shared__ __align__(16) __nv_bfloat16 sVl[32 * VSTRIDE];

    float acc[2][8][4];
#pragma unroll
    for (int i = 0; i < 2; i++) {
#pragma unroll
        for (int j = 0; j < 8; j++) {
#pragma unroll
            for (int q = 0; q < 4; q++) { acc[i][j][q] = 0.0f; }
        }
    }

    // loader roles
    const int pr  = tid >> 1;           // P row 0..127
    const int pcb = (tid & 1) * 16;     // P col base (floats)
    const int vk  = tid >> 3;           // V k-row 0..31
    const int vnb = (tid & 7) * 16;     // V col base (floats)

    const float* Prow = &g_P[((size_t)(b * SS + q0 + pr)) * SS];
    const float mrow = g_m[b * SS + q0 + pr];
    const float invl = 1.0f / g_l[b * SS + q0 + pr];

    const int nk = (rt + 1) * 4;        // number of k32 steps

    for (int kt = 0; kt < nk; kt++) {
        const int k0 = kt * 32;

        // stage P (fused exp/normalize + hi/lo split)
#pragma unroll
        for (int q4 = 0; q4 < 4; q4++) {
            float4 v = *(const float4*)&Prow[k0 + pcb + q4 * 4];
            float p0 = __expf(v.x - mrow) * invl;
            float p1 = __expf(v.y - mrow) * invl;
            float p2 = __expf(v.z - mrow) * invl;
            float p3 = __expf(v.w - mrow) * invl;
            float h0 = __bfloat162float(__float2bfloat16(p0));
            float h1 = __bfloat162float(__float2bfloat16(p1));
            float h2 = __bfloat162float(__float2bfloat16(p2));
            float h3 = __bfloat162float(__float2bfloat16(p3));
            uint32_t* dh = (uint32_t*)&sPh[pr * PSTRIDE + pcb + q4 * 4];
            uint32_t* dl = (uint32_t*)&sPl[pr * PSTRIDE + pcb + q4 * 4];
            dh[0] = pack2bf(h0, h1);
            dh[1] = pack2bf(h2, h3);
            dl[0] = pack2bf(p0 - h0, p1 - h1);
            dl[1] = pack2bf(p2 - h2, p3 - h3);
        }

        // stage V (hi/lo split)
#pragma unroll
        for (int q4 = 0; q4 < 4; q4++) {
            float4 v = *(const float4*)&enc[((size_t)(b * SS + k0 + vk)) * DD + c0 + vnb + q4 * 4];
            float h0 = __bfloat162float(__float2bfloat16(v.x));
            float h1 = __bfloat162float(__float2bfloat16(v.y));
            float h2 = __bfloat162float(__float2bfloat16(v.z));
            float h3 = __bfloat162float(__float2bfloat16(v.w));
            uint32_t* dh = (uint32_t*)&sVh[vk * VSTRIDE + vnb + q4 * 4];
            uint32_t* dl = (uint32_t*)&sVl[vk * VSTRIDE + vnb + q4 * 4];
            dh[0] = pack2bf(h0, h1);
            dh[1] = pack2bf(h2, h3);
            dl[0] = pack2bf(v.x - h0, v.y - h1);
            dl[1] = pack2bf(v.z - h2, v.w - h3);
        }
        __syncthreads();

        // tensor compute: two k16 sub-steps
#pragma unroll
        for (int s16 = 0; s16 < 2; s16++) {
            const int arow = lane & 15;
            const int ak = s16 * 16 + (lane >> 4) * 8;
            uint32_t ah0[4];
            uint32_t ah1[4];
            uint32_t al0[4];
            uint32_t al1[4];
            ldsm4(ah0, &sPh[(wm + arow) * PSTRIDE + ak]);
            ldsm4(ah1, &sPh[(wm + 16 + arow) * PSTRIDE + ak]);
            ldsm4(al0, &sPl[(wm + arow) * PSTRIDE + ak]);
            ldsm4(al1, &sPl[(wm + 16 + arow) * PSTRIDE + ak]);

#pragma unroll
            for (int nb = 0; nb < 4; nb++) {
                const int bofs = (s16 * 16 + (lane & 15)) * VSTRIDE
                               + wn + nb * 16 + (lane >> 4) * 8;
                uint32_t bh[4];
                uint32_t bl[4];
                ldsm4t(bh, &sVh[bofs]);
                ldsm4t(bl, &sVl[bofs]);

                float* cp0 = acc[0][nb * 2];
                float* cp1 = acc[0][nb * 2 + 1];
                float* cp2 = acc[1][nb * 2];
                float* cp3 = acc[1][nb * 2 + 1];

                mma16816(cp0, ah0, bh[0], bh[1]);
                mma16816(cp0, al0, bh[0], bh[1]);
                mma16816(cp0, ah0, bl[0], bl[1]);
                mma16816(cp1, ah0, bh[2], bh[3]);
                mma16816(cp1, al0, bh[2], bh[3]);
                mma16816(cp1, ah0, bl[2], bl[3]);
                mma16816(cp2, ah1, bh[0], bh[1]);
                mma16816(cp2, al1, bh[0], bh[1]);
                mma16816(cp2, ah1, bl[0], bl[1]);
                mma16816(cp3, ah1, bh[2], bh[3]);
                mma16816(cp3, al1, bh[2], bh[3]);
                mma16816(cp3, ah1, bl[2], bl[3]);
            }
        }
        __syncthreads();
    }

    // epilogue
#pragma unroll
    for (int mi = 0; mi < 2; mi++) {
        const int r0 = q0 + wm + mi * 16 + (lane >> 2);
#pragma unroll
        for (int nb8 = 0; nb8 < 8; nb8++) {
            const int cc = c0 + wn + nb8 * 8 + (lane & 3) * 2;
            float2* o0 = (float2*)&out[((size_t)(b * SS + r0)) * DD + cc];
            float2* o1 = (float2*)&out[((size_t)(b * SS + r0 + 8)) * DD + cc];
            o0->x = acc[mi][nb8][0];
            o0->y = acc[mi][nb8][1];
            o1->x = acc[mi][nb8][2];
            o1->y = acc[mi][nb8][3];
        }
    }
}

// =====================================================================
extern "C" void kernel_launch(void* const* d_in, const int* in_sizes, int n_in,
                              void* d_out, int out_size) {
    (void)in_sizes; (void)n_in; (void)out_size;
    const float* enc = (const float*)d_in[0];
    const float* Wq  = (const float*)d_in[1];
    const float* Wk  = (const float*)d_in[2];
    float* out = (float*)d_out;

    proj_kernel<<<dim3((BB * SS) / 64), 256>>>(enc, Wq, Wk);
    score_kernel<<<dim3(SS / 64, BB), 256>>>();
    pv_kernel<<<dim3(DD / 128, SS / 128, BB), 256>>>(enc, out);
}